// round 4
// baseline (speedup 1.0000x reference)
#include <cuda_runtime.h>
#include <cuda_bf16.h>
#include <cstdint>

#define NIN   128
#define HID   256
#define NB    16
#define NOUT  2048
#define TM    128

// SMEM layout (bytes):
//   sHi  @ 0      : 128*132*4 = 67584   (inter hi pairs stride 68, then h hi pairs stride 132)
//   sLo  @ 67584  : 67584
//   sBas @ 135168 : 128*17*4 = 8704
//   sOut @ 143872 : 128*132*4 = 67584
#define SMEM_BYTES 211456

// -------- device scratch (no cudaMalloc allowed) --------
__device__ unsigned g_W1hi[64 * HID];     // W1 [128,256] -> k-pair packed bf16 hi
__device__ unsigned g_W1lo[64 * HID];
__device__ unsigned g_W2hi[128 * NOUT];   // W2 [256,2048] -> k-pair packed bf16 hi
__device__ unsigned g_W2lo[128 * NOUT];
__device__ int g_idx64;

// -------- helpers --------
__device__ __forceinline__ unsigned pk(float x0, float x1, unsigned &lo) {
    __nv_bfloat16 h0 = __float2bfloat16(x0), h1 = __float2bfloat16(x1);
    float r0 = x0 - __bfloat162float(h0);
    float r1 = x1 - __bfloat162float(h1);
    __nv_bfloat16 l0 = __float2bfloat16(r0), l1 = __float2bfloat16(r1);
    lo = ((unsigned)__bfloat16_as_ushort(l1) << 16) | (unsigned)__bfloat16_as_ushort(l0);
    return ((unsigned)__bfloat16_as_ushort(h1) << 16) | (unsigned)__bfloat16_as_ushort(h0);
}

__device__ __forceinline__ void mma16816(float (&d)[4], const unsigned (&a)[4], const unsigned (&b)[2]) {
    asm volatile(
        "mma.sync.aligned.m16n8k16.row.col.f32.bf16.bf16.f32 "
        "{%0,%1,%2,%3},{%4,%5,%6,%7},{%8,%9},{%0,%1,%2,%3};\n"
        : "+f"(d[0]), "+f"(d[1]), "+f"(d[2]), "+f"(d[3])
        : "r"(a[0]), "r"(a[1]), "r"(a[2]), "r"(a[3]), "r"(b[0]), "r"(b[1]));
}

// -------- prep kernels --------
__global__ void detect_idx_kernel(const unsigned* __restrict__ idx_raw) {
    if (threadIdx.x == 0) {
        unsigned nz = 0;
        #pragma unroll 1
        for (int k = 0; k < 64; k++) nz |= idx_raw[2 * k + 1];
        g_idx64 = (nz == 0) ? 1 : 0;  // int64 values < 2^31 -> high words all zero
    }
}

__global__ void prep_w1_kernel(const float* __restrict__ W1) {
    int i = blockIdx.x * blockDim.x + threadIdx.x;
    if (i >= 64 * HID) return;
    int k2 = i / HID, n = i % HID;
    float x0 = W1[(2 * k2) * HID + n];
    float x1 = W1[(2 * k2 + 1) * HID + n];
    unsigned lo; unsigned hi = pk(x0, x1, lo);
    g_W1hi[i] = hi; g_W1lo[i] = lo;
}

__global__ void prep_w2_kernel(const float* __restrict__ W2) {
    int i = blockIdx.x * blockDim.x + threadIdx.x;
    if (i >= 128 * NOUT) return;
    int k2 = i / NOUT, n = i % NOUT;
    float x0 = W2[(2 * k2) * NOUT + n];
    float x1 = W2[(2 * k2 + 1) * NOUT + n];
    unsigned lo; unsigned hi = pk(x0, x1, lo);
    g_W2hi[i] = hi; g_W2lo[i] = lo;
}

// -------- main fused kernel: one CTA per 128-edge tile --------
__global__ void __launch_bounds__(256, 1) pilayer_kernel(
    const float* __restrict__ prop, const void* __restrict__ idxi_raw,
    const void* __restrict__ idxj_raw, const float* __restrict__ basis,
    float* __restrict__ out, int P)
{
    extern __shared__ char smem[];
    unsigned* sHi = (unsigned*)smem;
    unsigned* sLo = (unsigned*)(smem + 67584);
    float*    sBas = (float*)(smem + 135168);
    float*    sOut = (float*)(smem + 143872);

    const int tid = threadIdx.x;
    const int w = tid >> 5, lane = tid & 31, q = lane & 3, r = lane >> 2;
    const int m0 = blockIdx.x * TM;
    const int mvalid = min(TM, P - m0);
    const bool is64 = (g_idx64 != 0);

    // ---- gather: inter = prop[idx_i] + prop[idx_j]; split bf16 hi/lo, pack k-pairs ----
    {
        int m = tid >> 1, half = tid & 1;
        unsigned* dh = sHi + m * 68 + half * 32;
        unsigned* dl = sLo + m * 68 + half * 32;
        if (m < mvalid) {
            long e = (long)(m0 + m);
            long ii, jj;
            if (is64) { ii = ((const long long*)idxi_raw)[e]; jj = ((const long long*)idxj_raw)[e]; }
            else      { ii = ((const int*)idxi_raw)[e];       jj = ((const int*)idxj_raw)[e]; }
            const float4* pi = (const float4*)(prop + ii * NIN) + half * 16;
            const float4* pj = (const float4*)(prop + jj * NIN) + half * 16;
            #pragma unroll
            for (int v = 0; v < 16; v++) {
                float4 a = pi[v]; float4 b = pj[v];
                unsigned lo0, lo1;
                unsigned hi0 = pk(a.x + b.x, a.y + b.y, lo0);
                unsigned hi1 = pk(a.z + b.z, a.w + b.w, lo1);
                dh[2 * v] = hi0; dh[2 * v + 1] = hi1;
                dl[2 * v] = lo0; dl[2 * v + 1] = lo1;
            }
        } else {
            #pragma unroll
            for (int v = 0; v < 32; v++) { dh[v] = 0u; dl[v] = 0u; }
        }
        // basis rows (zero-padded past mvalid)
        int off = half * 8;
        float4 b0, b1;
        if (m < mvalid) {
            const float4* bp = (const float4*)(basis + (long)(m0 + m) * NB + off);
            b0 = bp[0]; b1 = bp[1];
        } else { b0 = make_float4(0.f, 0.f, 0.f, 0.f); b1 = b0; }
        float* bd = sBas + m * 17 + off;
        bd[0] = b0.x; bd[1] = b0.y; bd[2] = b0.z; bd[3] = b0.w;
        bd[4] = b1.x; bd[5] = b1.y; bd[6] = b1.z; bd[7] = b1.w;
    }
    __syncthreads();

    float acc[8][4][4];

    // ---- GEMM1: pre = inter @ W1  (M=128, N=256, K=128), bf16x3 ----
    #pragma unroll
    for (int mt = 0; mt < 8; mt++)
        #pragma unroll
        for (int nt = 0; nt < 4; nt++)
            #pragma unroll
            for (int e = 0; e < 4; e++) acc[mt][nt][e] = 0.f;

    const int ncol0 = w * 32 + r;
    #pragma unroll 1
    for (int ks = 0; ks < 8; ks++) {
        const int kp = ks * 8;
        unsigned bhi[4][2], blo[4][2];
        #pragma unroll
        for (int nt = 0; nt < 4; nt++) {
            int c0 = (kp + q) * HID + ncol0 + nt * 8;
            int c1 = (kp + 4 + q) * HID + ncol0 + nt * 8;
            bhi[nt][0] = g_W1hi[c0]; bhi[nt][1] = g_W1hi[c1];
            blo[nt][0] = g_W1lo[c0]; blo[nt][1] = g_W1lo[c1];
        }
        #pragma unroll
        for (int mt = 0; mt < 8; mt++) {
            unsigned ahi[4], alo[4];
            const unsigned* p0 = sHi + (mt * 16 + r) * 68 + kp + q;
            const unsigned* p1 = sHi + (mt * 16 + r + 8) * 68 + kp + q;
            ahi[0] = p0[0]; ahi[1] = p1[0]; ahi[2] = p0[4]; ahi[3] = p1[4];
            const unsigned* q0 = sLo + (mt * 16 + r) * 68 + kp + q;
            const unsigned* q1 = sLo + (mt * 16 + r + 8) * 68 + kp + q;
            alo[0] = q0[0]; alo[1] = q1[0]; alo[2] = q0[4]; alo[3] = q1[4];
            #pragma unroll
            for (int nt = 0; nt < 4; nt++) {
                mma16816(acc[mt][nt], ahi, bhi[nt]);
                mma16816(acc[mt][nt], ahi, blo[nt]);
                mma16816(acc[mt][nt], alo, bhi[nt]);
            }
        }
    }
    __syncthreads();  // all inter reads complete before h overwrites the region

    // ---- tanh + split + store h (k-pair packed, stride 132) ----
    #pragma unroll
    for (int mt = 0; mt < 8; mt++) {
        int row0 = mt * 16 + r;
        #pragma unroll
        for (int nt = 0; nt < 4; nt++) {
            int cp = w * 16 + nt * 4 + q;  // k-pair index in [0,128)
            unsigned lo;
            unsigned hi = pk(tanhf(acc[mt][nt][0]), tanhf(acc[mt][nt][1]), lo);
            sHi[row0 * 132 + cp] = hi; sLo[row0 * 132 + cp] = lo;
            hi = pk(tanhf(acc[mt][nt][2]), tanhf(acc[mt][nt][3]), lo);
            sHi[(row0 + 8) * 132 + cp] = hi; sLo[(row0 + 8) * 132 + cp] = lo;
        }
    }
    __syncthreads();

    // ---- GEMM2 (M=128, N=2048 in 8 passes of 256, K=256) + fused basis epilogue ----
    #pragma unroll 1
    for (int pass = 0; pass < 8; pass++) {
        #pragma unroll
        for (int mt = 0; mt < 8; mt++)
            #pragma unroll
            for (int nt = 0; nt < 4; nt++)
                #pragma unroll
                for (int e = 0; e < 4; e++) acc[mt][nt][e] = 0.f;

        const int jbase = pass * 256 + w * 32 + r;
        #pragma unroll 1
        for (int ks = 0; ks < 16; ks++) {
            const int kp = ks * 8;
            unsigned bhi[4][2], blo[4][2];
            #pragma unroll
            for (int nt = 0; nt < 4; nt++) {
                int c0 = (kp + q) * NOUT + jbase + nt * 8;
                int c1 = (kp + 4 + q) * NOUT + jbase + nt * 8;
                bhi[nt][0] = g_W2hi[c0]; bhi[nt][1] = g_W2hi[c1];
                blo[nt][0] = g_W2lo[c0]; blo[nt][1] = g_W2lo[c1];
            }
            #pragma unroll
            for (int mt = 0; mt < 8; mt++) {
                unsigned ahi[4], alo[4];
                const unsigned* p0 = sHi + (mt * 16 + r) * 132 + kp + q;
                const unsigned* p1 = sHi + (mt * 16 + r + 8) * 132 + kp + q;
                ahi[0] = p0[0]; ahi[1] = p1[0]; ahi[2] = p0[4]; ahi[3] = p1[4];
                const unsigned* q0 = sLo + (mt * 16 + r) * 132 + kp + q;
                const unsigned* q1 = sLo + (mt * 16 + r + 8) * 132 + kp + q;
                alo[0] = q0[0]; alo[1] = q1[0]; alo[2] = q0[4]; alo[3] = q1[4];
                #pragma unroll
                for (int nt = 0; nt < 4; nt++) {
                    mma16816(acc[mt][nt], ahi, bhi[nt]);
                    mma16816(acc[mt][nt], ahi, blo[nt]);
                    mma16816(acc[mt][nt], alo, bhi[nt]);
                }
            }
        }
        // epilogue: out[m][c] = sum_b H[m][16c+b]*basis[m][b]; each (pass,warp,tp) owns c exclusively
        #pragma unroll
        for (int mt = 0; mt < 8; mt++) {
            int row0 = mt * 16 + r, row1 = row0 + 8;
            float b00 = sBas[row0 * 17 + 2 * q],     b01 = sBas[row0 * 17 + 2 * q + 1];
            float b08 = sBas[row0 * 17 + 8 + 2 * q], b09 = sBas[row0 * 17 + 9 + 2 * q];
            float b10 = sBas[row1 * 17 + 2 * q],     b11 = sBas[row1 * 17 + 2 * q + 1];
            float b18 = sBas[row1 * 17 + 8 + 2 * q], b19 = sBas[row1 * 17 + 9 + 2 * q];
            #pragma unroll
            for (int tp = 0; tp < 2; tp++) {
                float s0 = acc[mt][2 * tp][0] * b00 + acc[mt][2 * tp][1] * b01
                         + acc[mt][2 * tp + 1][0] * b08 + acc[mt][2 * tp + 1][1] * b09;
                float s1 = acc[mt][2 * tp][2] * b10 + acc[mt][2 * tp][3] * b11
                         + acc[mt][2 * tp + 1][2] * b18 + acc[mt][2 * tp + 1][3] * b19;
                s0 += __shfl_xor_sync(0xffffffffu, s0, 1);
                s0 += __shfl_xor_sync(0xffffffffu, s0, 2);
                s1 += __shfl_xor_sync(0xffffffffu, s1, 1);
                s1 += __shfl_xor_sync(0xffffffffu, s1, 2);
                if (q == 0) {
                    int c = pass * 16 + w * 2 + tp;
                    sOut[row0 * 132 + c] = s0;
                    sOut[row1 * 132 + c] = s1;
                }
            }
        }
    }
    __syncthreads();

    // ---- coalesced output store ----
    #pragma unroll 1
    for (int i = tid; i < TM * 32; i += 256) {
        int m = i >> 5, c4 = i & 31;
        if (m < mvalid) {
            const float4 v = *(const float4*)(sOut + m * 132 + c4 * 4);
            *(float4*)(out + ((long)(m0 + m)) * NIN + c4 * 4) = v;
        }
    }
}

extern "C" void kernel_launch(void* const* d_in, const int* in_sizes, int n_in,
                              void* d_out, int out_size) {
    const float* prop  = (const float*)d_in[0];
    const void*  idxi  = d_in[1];
    const void*  idxj  = d_in[2];
    const float* basis = (const float*)d_in[3];
    const float* W1    = (const float*)d_in[4];
    const float* W2    = (const float*)d_in[5];
    float* out = (float*)d_out;
    const int P = out_size / NIN;
    (void)in_sizes; (void)n_in;

    cudaFuncSetAttribute(pilayer_kernel, cudaFuncAttributeMaxDynamicSharedMemorySize, SMEM_BYTES);

    detect_idx_kernel<<<1, 32>>>((const unsigned*)idxi);
    prep_w1_kernel<<<(64 * HID + 255) / 256, 256>>>(W1);
    prep_w2_kernel<<<(128 * NOUT + 255) / 256, 256>>>(W2);

    const int blocks = (P + TM - 1) / TM;
    pilayer_kernel<<<blocks, 256, SMEM_BYTES>>>(prop, idxi, idxj, basis, out, P);
}

// round 6
// speedup vs baseline: 1.0482x; 1.0482x over previous
#include <cuda_runtime.h>
#include <cuda_bf16.h>
#include <cstdint>

#define NIN 128
#define TM  128

// ---- SMEM map (bytes) ----
// A tiles: 16x16 bf16 tiles, 512B each, XOR-swizzled rows.
//   GEMM1 (inter): tile index = mt*8 + kc   (64 tiles, 32KB per hi/lo)
//   GEMM2 (h)    : tile index = mt*16 + kc  (128 tiles, 64KB per hi/lo)
#define OFF_AHI 0
#define OFF_ALO 65536
#define OFF_BAS 131072                // 128 * 17 * 4 = 8704
#define OFF_OUT 139776                // 128 * 132 * 4 = 67584
#define SMEM_BYTES 207360

// ---- device scratch: fragment-ordered bf16x2-split weights ----
__device__ __align__(16) unsigned g_W1v_hi[16384];
__device__ __align__(16) unsigned g_W1v_lo[16384];
__device__ __align__(16) unsigned g_W2v_hi[262144];
__device__ __align__(16) unsigned g_W2v_lo[262144];
__device__ int g_idx64;

// -------- helpers --------
__device__ __forceinline__ uint32_t smem_u32(const void* p) {
    uint32_t a;
    asm("{ .reg .u64 t; cvta.to.shared.u64 t, %1; cvt.u32.u64 %0, t; }" : "=r"(a) : "l"(p));
    return a;
}
__device__ __forceinline__ unsigned pk(float x0, float x1, unsigned& lo) {
    __nv_bfloat16 h0 = __float2bfloat16(x0), h1 = __float2bfloat16(x1);
    float r0 = x0 - __bfloat162float(h0);
    float r1 = x1 - __bfloat162float(h1);
    __nv_bfloat16 l0 = __float2bfloat16(r0), l1 = __float2bfloat16(r1);
    lo = ((unsigned)__bfloat16_as_ushort(l1) << 16) | (unsigned)__bfloat16_as_ushort(l0);
    return ((unsigned)__bfloat16_as_ushort(h1) << 16) | (unsigned)__bfloat16_as_ushort(h0);
}
__device__ __forceinline__ void st128s(uint32_t a, unsigned x, unsigned y, unsigned z, unsigned w) {
    asm volatile("st.shared.v4.b32 [%0], {%1,%2,%3,%4};" :: "r"(a), "r"(x), "r"(y), "r"(z), "r"(w) : "memory");
}
__device__ __forceinline__ void sts32(uint32_t a, unsigned v) {
    asm volatile("st.shared.b32 [%0], %1;" :: "r"(a), "r"(v) : "memory");
}
__device__ __forceinline__ void ldm4(unsigned (&a)[4], uint32_t addr) {
    asm volatile("ldmatrix.sync.aligned.m8n8.x4.shared.b16 {%0,%1,%2,%3}, [%4];"
                 : "=r"(a[0]), "=r"(a[1]), "=r"(a[2]), "=r"(a[3]) : "r"(addr));
}
__device__ __forceinline__ void mma4(float (&d)[4], const unsigned (&a)[4], unsigned b0, unsigned b1) {
    asm volatile(
        "mma.sync.aligned.m16n8k16.row.col.f32.bf16.bf16.f32 "
        "{%0,%1,%2,%3},{%4,%5,%6,%7},{%8,%9},{%0,%1,%2,%3};\n"
        : "+f"(d[0]), "+f"(d[1]), "+f"(d[2]), "+f"(d[3])
        : "r"(a[0]), "r"(a[1]), "r"(a[2]), "r"(a[3]), "r"(b0), "r"(b1));
}

// -------- prep kernels --------
__global__ void detect_idx_kernel(const unsigned* __restrict__ idx_raw) {
    if (threadIdx.x == 0) {
        unsigned nz = 0;
        #pragma unroll 1
        for (int k = 0; k < 64; k++) nz |= idx_raw[2 * k + 1];
        g_idx64 = (nz == 0) ? 1 : 0;  // int64 values < 2^31 -> high words all zero
    }
}

// W1 [128,256] -> per-(ks,w,lane) 8-word fragments (2x LDG.128 per k-step)
__global__ void prep_w1_kernel(const float* __restrict__ W1) {
    int i = blockIdx.x * 256 + threadIdx.x;        // 16384
    int e = i & 7, lane = (i >> 3) & 31, w = (i >> 8) & 7, ks = i >> 11;
    int q = lane & 3, r = lane >> 2;
    int kpair = ks * 8 + (e & 1) * 4 + q;
    int col = w * 32 + r + (e >> 1) * 8;
    float x0 = W1[(2 * kpair) * 256 + col];
    float x1 = W1[(2 * kpair + 1) * 256 + col];
    unsigned lo, hi = pk(x0, x1, lo);
    g_W1v_hi[i] = hi; g_W1v_lo[i] = lo;
}

// W2 [256,2048] -> per-(pass,ks,w,lane) fragments
__global__ void prep_w2_kernel(const float* __restrict__ W2) {
    int i = blockIdx.x * 256 + threadIdx.x;        // 262144
    int e = i & 7, lane = (i >> 3) & 31, w = (i >> 8) & 7;
    int ks = (i >> 11) & 15, pass = i >> 15;
    int q = lane & 3, r = lane >> 2;
    int kpair = ks * 8 + (e & 1) * 4 + q;
    int col = pass * 256 + w * 32 + r + (e >> 1) * 8;
    float x0 = W2[(2 * kpair) * 2048 + col];
    float x1 = W2[(2 * kpair + 1) * 2048 + col];
    unsigned lo, hi = pk(x0, x1, lo);
    g_W2v_hi[i] = hi; g_W2v_lo[i] = lo;
}

// -------- main fused kernel: one CTA per 128-edge tile --------
__global__ void __launch_bounds__(256, 1) pilayer_kernel(
    const float* __restrict__ prop, const void* __restrict__ idxi_raw,
    const void* __restrict__ idxj_raw, const float* __restrict__ basis,
    float* __restrict__ out, int P)
{
    extern __shared__ __align__(1024) char smem[];
    const uint32_t su = smem_u32(smem);
    float* sBas = (float*)(smem + OFF_BAS);
    float* sOut = (float*)(smem + OFF_OUT);

    const int tid = threadIdx.x;
    const int w = tid >> 5, lane = tid & 31, q = lane & 3, r = lane >> 2;
    const int m0 = blockIdx.x * TM;
    const int mvalid = min(TM, P - m0);
    const bool is64 = (g_idx64 != 0);

    // per-lane ldmatrix offset within a 512B tile
    const int rL = (lane & 7) + (lane & 8);
    const int hL = lane >> 4;
    const uint32_t lmoff = (uint32_t)((rL * 32 + hL * 16) ^ ((rL & 4) << 2));
    const uint32_t aHiB = su + OFF_AHI + lmoff;
    const uint32_t aLoB = su + OFF_ALO + lmoff;

    // ---- gather: inter = prop[idx_i] + prop[idx_j]; bf16 hi/lo split, swizzled tiles ----
    {
        const int m = tid >> 1, half = tid & 1;
        const int mt = m >> 4, rr = m & 15;
        const unsigned swz = (unsigned)((rr & 4) << 2);
        const uint32_t o0 = (uint32_t)((rr * 32) ^ swz);
        const uint32_t o1 = o0 ^ 16u;
        if (m < mvalid) {
            long long e = (long long)(m0 + m);
            long long ia, ja;
            if (is64) { ia = ((const long long*)idxi_raw)[e]; ja = ((const long long*)idxj_raw)[e]; }
            else      { ia = ((const int*)idxi_raw)[e];       ja = ((const int*)idxj_raw)[e]; }
            const float4* pi = (const float4*)(prop + ia * NIN);
            const float4* pj = (const float4*)(prop + ja * NIN);
            #pragma unroll
            for (int kc = 0; kc < 4; kc++) {
                const int kcg = half * 4 + kc;
                const uint32_t tb = (uint32_t)((mt * 8 + kcg) * 512);
                float4 A0 = pi[kcg * 4], A1 = pi[kcg * 4 + 1], A2 = pi[kcg * 4 + 2], A3 = pi[kcg * 4 + 3];
                float4 B0 = pj[kcg * 4], B1 = pj[kcg * 4 + 1], B2 = pj[kcg * 4 + 2], B3 = pj[kcg * 4 + 3];
                unsigned h0, h1, h2, h3, h4, h5, h6, h7, l0, l1, l2, l3, l4, l5, l6, l7;
                h0 = pk(A0.x + B0.x, A0.y + B0.y, l0);
                h1 = pk(A0.z + B0.z, A0.w + B0.w, l1);
                h2 = pk(A1.x + B1.x, A1.y + B1.y, l2);
                h3 = pk(A1.z + B1.z, A1.w + B1.w, l3);
                h4 = pk(A2.x + B2.x, A2.y + B2.y, l4);
                h5 = pk(A2.z + B2.z, A2.w + B2.w, l5);
                h6 = pk(A3.x + B3.x, A3.y + B3.y, l6);
                h7 = pk(A3.z + B3.z, A3.w + B3.w, l7);
                st128s(su + OFF_AHI + tb + o0, h0, h1, h2, h3);
                st128s(su + OFF_AHI + tb + o1, h4, h5, h6, h7);
                st128s(su + OFF_ALO + tb + o0, l0, l1, l2, l3);
                st128s(su + OFF_ALO + tb + o1, l4, l5, l6, l7);
            }
        } else {
            #pragma unroll
            for (int kc = 0; kc < 4; kc++) {
                const uint32_t tb = (uint32_t)((mt * 8 + half * 4 + kc) * 512);
                st128s(su + OFF_AHI + tb + o0, 0, 0, 0, 0);
                st128s(su + OFF_AHI + tb + o1, 0, 0, 0, 0);
                st128s(su + OFF_ALO + tb + o0, 0, 0, 0, 0);
                st128s(su + OFF_ALO + tb + o1, 0, 0, 0, 0);
            }
        }
        // basis rows (zero-padded past mvalid)
        const int off = half * 8;
        float4 b0, b1;
        if (m < mvalid) {
            const float4* bp = (const float4*)(basis + (size_t)(m0 + m) * 16 + off);
            b0 = bp[0]; b1 = bp[1];
        } else { b0 = make_float4(0.f, 0.f, 0.f, 0.f); b1 = b0; }
        float* bd = sBas + m * 17 + off;
        bd[0] = b0.x; bd[1] = b0.y; bd[2] = b0.z; bd[3] = b0.w;
        bd[4] = b1.x; bd[5] = b1.y; bd[6] = b1.z; bd[7] = b1.w;
    }
    __syncthreads();

    float acc[8][4][4];
    #pragma unroll
    for (int mt = 0; mt < 8; mt++)
        #pragma unroll
        for (int nt = 0; nt < 4; nt++)
            #pragma unroll
            for (int e = 0; e < 4; e++) acc[mt][nt][e] = 0.f;

    const unsigned* pW1h = g_W1v_hi + (w * 32 + lane) * 8;
    const unsigned* pW1l = g_W1v_lo + (w * 32 + lane) * 8;
    const unsigned* pW2h = g_W2v_hi + (w * 32 + lane) * 8;
    const unsigned* pW2l = g_W2v_lo + (w * 32 + lane) * 8;

    uint4 bh0 = *(const uint4*)(pW1h), bh1 = *(const uint4*)(pW1h + 4);
    uint4 bl0 = *(const uint4*)(pW1l), bl1 = *(const uint4*)(pW1l + 4);

    // ---- GEMM1: pre = inter @ W1 (M=128, N=256, K=128), bf16x3 ----
    #pragma unroll 1
    for (int ks = 0; ks < 8; ks++) {
        const unsigned* nh = (ks < 7) ? (pW1h + (ks + 1) * 2048) : pW2h;
        const unsigned* nl = (ks < 7) ? (pW1l + (ks + 1) * 2048) : pW2l;
        uint4 nh0 = *(const uint4*)(nh), nh1 = *(const uint4*)(nh + 4);
        uint4 nl0 = *(const uint4*)(nl), nl1 = *(const uint4*)(nl + 4);
        const unsigned Bh[4][2] = {{bh0.x, bh0.y}, {bh0.z, bh0.w}, {bh1.x, bh1.y}, {bh1.z, bh1.w}};
        const unsigned Bl[4][2] = {{bl0.x, bl0.y}, {bl0.z, bl0.w}, {bl1.x, bl1.y}, {bl1.z, bl1.w}};
        #pragma unroll
        for (int mt = 0; mt < 8; mt++) {
            unsigned ahi[4], alo[4];
            ldm4(ahi, aHiB + (uint32_t)((mt * 8 + ks) * 512));
            ldm4(alo, aLoB + (uint32_t)((mt * 8 + ks) * 512));
            #pragma unroll
            for (int nt = 0; nt < 4; nt++) {
                mma4(acc[mt][nt], ahi, Bh[nt][0], Bh[nt][1]);
                mma4(acc[mt][nt], ahi, Bl[nt][0], Bl[nt][1]);
                mma4(acc[mt][nt], alo, Bh[nt][0], Bh[nt][1]);
            }
        }
        bh0 = nh0; bh1 = nh1; bl0 = nl0; bl1 = nl1;
    }
    __syncthreads();  // all inter reads complete before h overwrites the tile region

    // ---- tanh + split + store h tiles ----
    #pragma unroll
    for (int mt = 0; mt < 8; mt++) {
        #pragma unroll
        for (int nt = 0; nt < 4; nt++) {
            const int e = nt & 1;
            const uint32_t tb = (uint32_t)((mt * 16 + 2 * w + (nt >> 1)) * 512);
            const int inrow = 16 * e + 4 * q;
            unsigned lo;
            unsigned hi = pk(tanhf(acc[mt][nt][0]), tanhf(acc[mt][nt][1]), lo);
            uint32_t o = (uint32_t)((r * 32 + inrow) ^ ((r & 4) << 2));
            sts32(su + OFF_AHI + tb + o, hi);
            sts32(su + OFF_ALO + tb + o, lo);
            hi = pk(tanhf(acc[mt][nt][2]), tanhf(acc[mt][nt][3]), lo);
            const int r1 = r + 8;
            o = (uint32_t)((r1 * 32 + inrow) ^ ((r1 & 4) << 2));
            sts32(su + OFF_AHI + tb + o, hi);
            sts32(su + OFF_ALO + tb + o, lo);
        }
    }
    #pragma unroll
    for (int mt = 0; mt < 8; mt++)
        #pragma unroll
        for (int nt = 0; nt < 4; nt++)
            #pragma unroll
            for (int e = 0; e < 4; e++) acc[mt][nt][e] = 0.f;
    __syncthreads();

    // ---- GEMM2 (M=128, N=2048 flattened: 128 k-steps, epilogue every 16) ----
    #pragma unroll 1
    for (int t = 0; t < 128; t++) {
        const int tn = (t < 127) ? (t + 1) : 0;
        const unsigned* nh = pW2h + tn * 2048;
        const unsigned* nl = pW2l + tn * 2048;
        uint4 nh0 = *(const uint4*)(nh), nh1 = *(const uint4*)(nh + 4);
        uint4 nl0 = *(const uint4*)(nl), nl1 = *(const uint4*)(nl + 4);
        const unsigned Bh[4][2] = {{bh0.x, bh0.y}, {bh0.z, bh0.w}, {bh1.x, bh1.y}, {bh1.z, bh1.w}};
        const unsigned Bl[4][2] = {{bl0.x, bl0.y}, {bl0.z, bl0.w}, {bl1.x, bl1.y}, {bl1.z, bl1.w}};
        const int kc = t & 15;
        #pragma unroll
        for (int mt = 0; mt < 8; mt++) {
            unsigned ahi[4], alo[4];
            ldm4(ahi, aHiB + (uint32_t)((mt * 16 + kc) * 512));
            ldm4(alo, aLoB + (uint32_t)((mt * 16 + kc) * 512));
            #pragma unroll
            for (int nt = 0; nt < 4; nt++) {
                mma4(acc[mt][nt], ahi, Bh[nt][0], Bh[nt][1]);
                mma4(acc[mt][nt], ahi, Bl[nt][0], Bl[nt][1]);
                mma4(acc[mt][nt], alo, Bh[nt][0], Bh[nt][1]);
            }
        }
        bh0 = nh0; bh1 = nh1; bl0 = nl0; bl1 = nl1;

        if (kc == 15) {
            const int pass = t >> 4;
            // epilogue: out[m][c] = sum_b H[m][16c+b]*basis[m][b]
            #pragma unroll
            for (int mt = 0; mt < 8; mt++) {
                const int row0 = mt * 16 + r, row1 = row0 + 8;
                float b00 = sBas[row0 * 17 + 2 * q],     b01 = sBas[row0 * 17 + 2 * q + 1];
                float b08 = sBas[row0 * 17 + 8 + 2 * q], b09 = sBas[row0 * 17 + 9 + 2 * q];
                float b10 = sBas[row1 * 17 + 2 * q],     b11 = sBas[row1 * 17 + 2 * q + 1];
                float b18 = sBas[row1 * 17 + 8 + 2 * q], b19 = sBas[row1 * 17 + 9 + 2 * q];
                #pragma unroll
                for (int tp = 0; tp < 2; tp++) {
                    float s0 = acc[mt][2 * tp][0] * b00 + acc[mt][2 * tp][1] * b01
                             + acc[mt][2 * tp + 1][0] * b08 + acc[mt][2 * tp + 1][1] * b09;
                    float s1 = acc[mt][2 * tp][2] * b10 + acc[mt][2 * tp][3] * b11
                             + acc[mt][2 * tp + 1][2] * b18 + acc[mt][2 * tp + 1][3] * b19;
                    s0 += __shfl_xor_sync(0xffffffffu, s0, 1);
                    s0 += __shfl_xor_sync(0xffffffffu, s0, 2);
                    s1 += __shfl_xor_sync(0xffffffffu, s1, 1);
                    s1 += __shfl_xor_sync(0xffffffffu, s1, 2);
                    if (q == 0) {
                        const int c = pass * 16 + w * 2 + tp;
                        sOut[row0 * 132 + c] = s0;
                        sOut[row1 * 132 + c] = s1;
                    }
                }
            }
            #pragma unroll
            for (int mt = 0; mt < 8; mt++)
                #pragma unroll
                for (int nt = 0; nt < 4; nt++)
                    #pragma unroll
                    for (int e = 0; e < 4; e++) acc[mt][nt][e] = 0.f;
        }
    }
    __syncthreads();

    // ---- coalesced output store ----
    #pragma unroll 1
    for (int i = tid; i < TM * 32; i += 256) {
        const int m = i >> 5, c4 = i & 31;
        if (m < mvalid) {
            const float4 v = *(const float4*)(sOut + m * 132 + c4 * 4);
            *(float4*)(out + ((size_t)(m0 + m)) * NIN + c4 * 4) = v;
        }
    }
}

extern "C" void kernel_launch(void* const* d_in, const int* in_sizes, int n_in,
                              void* d_out, int out_size) {
    const float* prop  = (const float*)d_in[0];
    const void*  idxi  = d_in[1];
    const void*  idxj  = d_in[2];
    const float* basis = (const float*)d_in[3];
    const float* W1    = (const float*)d_in[4];
    const float* W2    = (const float*)d_in[5];
    float* out = (float*)d_out;
    const int P = out_size / NIN;
    (void)in_sizes; (void)n_in;

    cudaFuncSetAttribute(pilayer_kernel, cudaFuncAttributeMaxDynamicSharedMemorySize, SMEM_BYTES);

    detect_idx_kernel<<<1, 32>>>((const unsigned*)idxi);
    prep_w1_kernel<<<64, 256>>>(W1);
    prep_w2_kernel<<<1024, 256>>>(W2);

    const int blocks = (P + TM - 1) / TM;
    pilayer_kernel<<<blocks, 256, SMEM_BYTES>>>(prop, idxi, idxj, basis, out, P);
}